// round 1
// baseline (speedup 1.0000x reference)
#include <cuda_runtime.h>
#include <cuda_bf16.h>
#include <math.h>

// Problem constants
#define BB   4
#define LL   2048
#define DD   768
#define DI   1536
#define DS   16
#define DR   48
#define KC   4
#define NCH  16          // scan chunks
#define CLEN (LL / NCH)  // 128 steps per chunk

// ---------------- scratch (device globals; no allocations allowed) ----------
__device__ float g_ada  [BB * 3 * DD];          // 9216
__device__ float g_xm   [BB * LL * DD];         // 6.3M
__device__ float g_xz   [(size_t)BB * LL * 2 * DI]; // 50.3M floats (xi | z)
__device__ float g_u    [(size_t)BB * LL * DI];
__device__ float g_dbl  [(size_t)BB * LL * 80];  // dt(48) | B(16) | C(16)
__device__ float g_delta[(size_t)BB * LL * DI];
__device__ float g_y    [(size_t)BB * LL * DI];
__device__ float g_hend [(size_t)BB * DI * NCH * DS];
__device__ float g_P    [(size_t)BB * DI * NCH * DS];
__device__ float g_hinit[(size_t)BB * DI * NCH * DS];

__device__ __forceinline__ float silu_f(float v) {
    return v / (1.0f + __expf(-v));
}

// ---------------- K1: ada = silu(c) @ ada_w^T + ada_b -----------------------
__global__ void ada_kernel(const float* __restrict__ c,
                           const float* __restrict__ ada_w,
                           const float* __restrict__ ada_b) {
    int warp = threadIdx.x >> 5, lane = threadIdx.x & 31;
    int j = blockIdx.x * 8 + warp;        // 0..2303
    int b = blockIdx.y;                   // 0..3
    const float* cr = c + b * (2 * DD);
    const float* wr = ada_w + (size_t)j * (2 * DD);
    float acc = 0.f;
    for (int k = lane; k < 2 * DD; k += 32) {
        float cv = cr[k];
        acc += (cv / (1.0f + __expf(-cv))) * wr[k];
    }
    #pragma unroll
    for (int o = 16; o; o >>= 1) acc += __shfl_down_sync(0xffffffffu, acc, o);
    if (lane == 0) g_ada[b * (3 * DD) + j] = acc + ada_b[j];
}

// ---------------- K2: LayerNorm + modulate ----------------------------------
__global__ void ln_mod_kernel(const float* __restrict__ x,
                              const float* __restrict__ lnw,
                              const float* __restrict__ lnb) {
    int row = blockIdx.x;            // b*L + l, 0..8191
    int b = row >> 11;               // L = 2048
    const float* xr = x + (size_t)row * DD;
    int tid = threadIdx.x;           // 256
    float s = 0.f, s2 = 0.f;
    #pragma unroll
    for (int i = 0; i < 3; i++) {
        float v = xr[tid + i * 256];
        s += v; s2 += v * v;
    }
    #pragma unroll
    for (int o = 16; o; o >>= 1) {
        s  += __shfl_down_sync(0xffffffffu, s,  o);
        s2 += __shfl_down_sync(0xffffffffu, s2, o);
    }
    __shared__ float rs[8], rs2[8];
    __shared__ float smu, srstd;
    int warp = tid >> 5, lane = tid & 31;
    if (lane == 0) { rs[warp] = s; rs2[warp] = s2; }
    __syncthreads();
    if (tid == 0) {
        float S = 0.f, S2 = 0.f;
        #pragma unroll
        for (int w = 0; w < 8; w++) { S += rs[w]; S2 += rs2[w]; }
        float mu = S * (1.0f / DD);
        float var = S2 * (1.0f / DD) - mu * mu;
        smu = mu; srstd = rsqrtf(var + 1e-5f);
    }
    __syncthreads();
    float mu = smu, rstd = srstd;
    const float* adab = g_ada + b * (3 * DD);
    #pragma unroll
    for (int i = 0; i < 3; i++) {
        int j = tid + i * 256;
        float v = (xr[j] - mu) * rstd * lnw[j] + lnb[j];
        g_xm[(size_t)row * DD + j] = v * (1.0f + adab[DD + j]) + adab[j];
    }
}

// ---------------- SGEMM: C[M,N] = A[M,K] * B[N,K]^T (both K-contiguous) -----
// MODE 0: plain; MODE 1: softplus(v + bias[n]); MODE 2: resid + gate * v
#define BMT 128
#define BNT 128
#define BKT 16

template <int MODE>
__global__ void __launch_bounds__(256)
sgemm_tn(int M, int N, int K,
         const float* __restrict__ A, int lda,
         const float* __restrict__ Bw, int ldb,
         float* __restrict__ C, int ldc,
         const float* __restrict__ bias,
         const float* __restrict__ resid) {
    __shared__ float As[BKT][BMT + 4];
    __shared__ float Bs[BKT][BNT + 4];
    const int bm = blockIdx.y * BMT;
    const int bn = blockIdx.x * BNT;
    const int tid = threadIdx.x;
    const int tx = tid & 15;
    const int ty = tid >> 4;

    float acc[8][8];
    #pragma unroll
    for (int i = 0; i < 8; i++)
        #pragma unroll
        for (int j = 0; j < 8; j++) acc[i][j] = 0.f;

    const int nk = K / BKT;
    for (int kt = 0; kt < nk; kt++) {
        const int k0 = kt * BKT;
        #pragma unroll
        for (int r = 0; r < 2; r++) {
            int slot = tid + r * 256;       // 0..511
            int row = slot >> 2;            // 0..127
            int kk = (slot & 3) << 2;       // 0,4,8,12
            float4 v = *reinterpret_cast<const float4*>(
                A + (size_t)(bm + row) * lda + k0 + kk);
            As[kk + 0][row] = v.x; As[kk + 1][row] = v.y;
            As[kk + 2][row] = v.z; As[kk + 3][row] = v.w;
            float4 w = make_float4(0.f, 0.f, 0.f, 0.f);
            if (bn + row < N)
                w = *reinterpret_cast<const float4*>(
                    Bw + (size_t)(bn + row) * ldb + k0 + kk);
            Bs[kk + 0][row] = w.x; Bs[kk + 1][row] = w.y;
            Bs[kk + 2][row] = w.z; Bs[kk + 3][row] = w.w;
        }
        __syncthreads();
        #pragma unroll
        for (int k = 0; k < BKT; k++) {
            float ar[8], br[8];
            *reinterpret_cast<float4*>(&ar[0]) = *reinterpret_cast<const float4*>(&As[k][ty * 8]);
            *reinterpret_cast<float4*>(&ar[4]) = *reinterpret_cast<const float4*>(&As[k][ty * 8 + 4]);
            *reinterpret_cast<float4*>(&br[0]) = *reinterpret_cast<const float4*>(&Bs[k][tx * 8]);
            *reinterpret_cast<float4*>(&br[4]) = *reinterpret_cast<const float4*>(&Bs[k][tx * 8 + 4]);
            #pragma unroll
            for (int i = 0; i < 8; i++)
                #pragma unroll
                for (int j = 0; j < 8; j++) acc[i][j] += ar[i] * br[j];
        }
        __syncthreads();
    }

    #pragma unroll
    for (int i = 0; i < 8; i++) {
        int m = bm + ty * 8 + i;
        #pragma unroll
        for (int j = 0; j < 8; j++) {
            int n = bn + tx * 8 + j;
            if (n < N) {
                float v = acc[i][j];
                if (MODE == 1) {
                    v += bias[n];
                    v = (v > 20.f) ? v : log1pf(expf(v));
                } else if (MODE == 2) {
                    int b = m >> 11;  // L = 2048
                    float gate = g_ada[b * (3 * DD) + 2 * DD + n];
                    v = resid[(size_t)m * ldc + n] + gate * v;
                }
                C[(size_t)m * ldc + n] = v;
            }
        }
    }
}

// ---------------- K4: depthwise causal conv (K=4) + silu --------------------
__global__ void conv_silu_kernel(const float* __restrict__ cw,
                                 const float* __restrict__ cb) {
    long long idx = (long long)blockIdx.x * 256 + threadIdx.x;
    if (idx >= (long long)BB * LL * DI) return;
    int d = (int)(idx % DI);
    long long bt = idx / DI;
    int t = (int)(bt % LL);
    int b = (int)(bt / LL);
    const float* base = g_xz + (size_t)b * LL * (2 * DI) + d;  // xi column d
    float w0 = cw[d * 4 + 0], w1 = cw[d * 4 + 1];
    float w2 = cw[d * 4 + 2], w3 = cw[d * 4 + 3];
    float acc = cb[d];
    if (t >= 3) acc += base[(size_t)(t - 3) * (2 * DI)] * w0;
    if (t >= 2) acc += base[(size_t)(t - 2) * (2 * DI)] * w1;
    if (t >= 1) acc += base[(size_t)(t - 1) * (2 * DI)] * w2;
    acc += base[(size_t)t * (2 * DI)] * w3;
    g_u[idx] = acc / (1.0f + __expf(-acc));
}

// ---------------- scan pass 1: local scan per chunk, record (h_end, P) ------
__global__ void __launch_bounds__(128) scan_pass1(const float* __restrict__ A_log) {
    int dblk = blockIdx.x;     // 0..11
    int ch = blockIdx.y;       // 0..15
    int b = blockIdx.z;        // 0..3
    int d = dblk * 128 + threadIdx.x;

    float a[DS], h[DS], P[DS];
    #pragma unroll
    for (int s = 0; s < DS; s++) {
        a[s] = -__expf(A_log[d * DS + s]);
        h[s] = 0.f;
        P[s] = 1.f;
    }
    __shared__ float sB[8][DS];
    int t0 = ch * CLEN;
    for (int tt = 0; tt < CLEN; tt += 8) {
        __syncthreads();
        {
            int li = threadIdx.x;          // 128 threads -> 8*16 values
            int trow = li >> 4, s = li & 15;
            sB[trow][s] = g_dbl[(size_t)(b * LL + t0 + tt + trow) * 80 + DR + s];
        }
        __syncthreads();
        #pragma unroll
        for (int q = 0; q < 8; q++) {
            int t = t0 + tt + q;
            size_t off = (size_t)(b * LL + t) * DI + d;
            float delta = g_delta[off];
            float uv = g_u[off];
            float du = delta * uv;
            #pragma unroll
            for (int s = 0; s < DS; s++) {
                float dA = __expf(delta * a[s]);
                P[s] *= dA;
                h[s] = dA * h[s] + du * sB[q][s];
            }
        }
    }
    size_t o = ((size_t)(b * DI + d) * NCH + ch) * DS;
    #pragma unroll
    for (int s = 0; s < DS; s++) { g_hend[o + s] = h[s]; g_P[o + s] = P[s]; }
}

// ---------------- scan pass 2: combine chunk states -------------------------
__global__ void scan_pass2() {
    int idx = blockIdx.x * 256 + threadIdx.x;  // (b*DI+d)*16 + s, total 98304
    if (idx >= BB * DI * DS) return;
    size_t base = (size_t)(idx >> 4) * (NCH * DS) + (idx & 15);
    float hi = 0.f;
    #pragma unroll
    for (int ch = 0; ch < NCH; ch++) {
        size_t o = base + (size_t)ch * DS;
        g_hinit[o] = hi;
        hi = g_P[o] * hi + g_hend[o];
    }
}

// ---------------- scan pass 3: full scan with init; fused epilogue ----------
__global__ void __launch_bounds__(128) scan_pass3(const float* __restrict__ A_log,
                                                  const float* __restrict__ Dp) {
    int dblk = blockIdx.x;
    int ch = blockIdx.y;
    int b = blockIdx.z;
    int d = dblk * 128 + threadIdx.x;

    float a[DS], h[DS];
    size_t hio = ((size_t)(b * DI + d) * NCH + ch) * DS;
    #pragma unroll
    for (int s = 0; s < DS; s++) {
        a[s] = -__expf(A_log[d * DS + s]);
        h[s] = g_hinit[hio + s];
    }
    float Dpd = Dp[d];
    __shared__ float sBC[8][32];   // B(16) | C(16), contiguous in g_dbl
    int t0 = ch * CLEN;
    for (int tt = 0; tt < CLEN; tt += 8) {
        __syncthreads();
        #pragma unroll
        for (int r = 0; r < 2; r++) {
            int q = threadIdx.x + r * 128;   // 0..255
            int trow = q >> 5, cc = q & 31;
            sBC[trow][cc] = g_dbl[(size_t)(b * LL + t0 + tt + trow) * 80 + DR + cc];
        }
        __syncthreads();
        #pragma unroll
        for (int q = 0; q < 8; q++) {
            int t = t0 + tt + q;
            size_t off = (size_t)(b * LL + t) * DI + d;
            float delta = g_delta[off];
            float uv = g_u[off];
            float du = delta * uv;
            float y = 0.f;
            #pragma unroll
            for (int s = 0; s < DS; s++) {
                float dA = __expf(delta * a[s]);
                h[s] = dA * h[s] + du * sBC[q][s];
                y += h[s] * sBC[q][DS + s];
            }
            float z = g_xz[(size_t)(b * LL + t) * (2 * DI) + DI + d];
            float yv = y + uv * Dpd;
            g_y[off] = yv * (z / (1.0f + __expf(-z)));
        }
    }
}

// ---------------- launch -----------------------------------------------------
extern "C" void kernel_launch(void* const* d_in, const int* in_sizes, int n_in,
                              void* d_out, int out_size) {
    const float* x         = (const float*)d_in[0];
    const float* c         = (const float*)d_in[1];
    const float* ln_w      = (const float*)d_in[2];
    const float* ln_b      = (const float*)d_in[3];
    const float* ada_w     = (const float*)d_in[4];
    const float* ada_b     = (const float*)d_in[5];
    const float* in_proj_w = (const float*)d_in[6];
    const float* conv_w    = (const float*)d_in[7];
    const float* conv_b    = (const float*)d_in[8];
    const float* x_proj_w  = (const float*)d_in[9];
    const float* dt_proj_w = (const float*)d_in[10];
    const float* dt_proj_b = (const float*)d_in[11];
    const float* A_log     = (const float*)d_in[12];
    const float* D_param   = (const float*)d_in[13];
    const float* out_proj_w= (const float*)d_in[14];
    float* out = (float*)d_out;

    float *p_xm, *p_xz, *p_u, *p_dbl, *p_delta, *p_y;
    cudaGetSymbolAddress((void**)&p_xm,    g_xm);
    cudaGetSymbolAddress((void**)&p_xz,    g_xz);
    cudaGetSymbolAddress((void**)&p_u,     g_u);
    cudaGetSymbolAddress((void**)&p_dbl,   g_dbl);
    cudaGetSymbolAddress((void**)&p_delta, g_delta);
    cudaGetSymbolAddress((void**)&p_y,     g_y);

    const int M = BB * LL;  // 8192

    // 1) ada
    ada_kernel<<<dim3(3 * DD / 8, BB), 256>>>(c, ada_w, ada_b);
    // 2) layernorm + modulate
    ln_mod_kernel<<<M, 256>>>(x, ln_w, ln_b);
    // 3) xz = xm @ in_proj_w^T    (8192 x 3072 x 768)
    sgemm_tn<0><<<dim3(3072 / BNT, M / BMT), 256>>>(
        M, 3072, DD, p_xm, DD, in_proj_w, DD, p_xz, 3072, nullptr, nullptr);
    // 4) depthwise conv + silu
    conv_silu_kernel<<<(BB * LL * DI + 255) / 256, 256>>>(conv_w, conv_b);
    // 5) dbl = u @ x_proj_w^T     (8192 x 80 x 1536)
    sgemm_tn<0><<<dim3(1, M / BMT), 256>>>(
        M, 80, DI, p_u, DI, x_proj_w, DI, p_dbl, 80, nullptr, nullptr);
    // 6) delta = softplus(dt @ dt_proj_w^T + b)   (8192 x 1536 x 48)
    sgemm_tn<1><<<dim3(DI / BNT, M / BMT), 256>>>(
        M, DI, DR, p_dbl, 80, dt_proj_w, DR, p_delta, DI, dt_proj_b, nullptr);
    // 7) chunked selective scan (3 passes), fused +u*D and *silu(z)
    scan_pass1<<<dim3(DI / 128, NCH, BB), 128>>>(A_log);
    scan_pass2<<<(BB * DI * DS + 255) / 256, 256>>>();
    scan_pass3<<<dim3(DI / 128, NCH, BB), 128>>>(A_log, D_param);
    // 8) out = x + gate * (y @ out_proj_w^T)   (8192 x 768 x 1536)
    sgemm_tn<2><<<dim3(DD / BNT, M / BMT), 256>>>(
        M, DD, DI, p_y, DI, out_proj_w, DI, out, DD, nullptr, x);
}

// round 8
// speedup vs baseline: 3.5644x; 3.5644x over previous
#include <cuda_runtime.h>
#include <cuda_bf16.h>
#include <cstdint>
#include <math.h>

// Problem constants
#define BB   4
#define LL   2048
#define DD   768
#define DI   1536
#define DS   16
#define DR   48
#define NCH  16
#define CLEN (LL / NCH)

// ---------------- scratch (device globals) ----------------------------------
__device__ float          g_ada  [BB * 3 * DD];
__device__ __nv_bfloat16  g_xm_bf[(size_t)BB * LL * DD];
__device__ __nv_bfloat16  g_xz_bf[(size_t)BB * LL * 2 * DI];
__device__ float          g_u    [(size_t)BB * LL * DI];
__device__ __nv_bfloat16  g_u_bf [(size_t)BB * LL * DI];
__device__ float          g_bc   [(size_t)BB * LL * 32];    // B(16)|C(16)
__device__ __nv_bfloat16  g_dt_bf[(size_t)BB * LL * 64];    // dt padded 48->64
__device__ float          g_delta[(size_t)BB * LL * DI];
__device__ __nv_bfloat16  g_y_bf [(size_t)BB * LL * DI];
__device__ float          g_hend [(size_t)BB * DI * NCH * DS];
__device__ float          g_P    [(size_t)BB * DI * NCH * DS];
__device__ float          g_hinit[(size_t)BB * DI * NCH * DS];
// bf16 weights
__device__ __nv_bfloat16  g_w1  [(size_t)(2 * DI) * DD];    // in_proj
__device__ __nv_bfloat16  g_w2  [(size_t)DD * DI];          // out_proj
__device__ __nv_bfloat16  g_xpw [(size_t)80 * DI];          // x_proj
__device__ __nv_bfloat16  g_dtw [(size_t)DI * 64];          // dt_proj padded

// ---------------- PTX helpers ------------------------------------------------
__device__ __forceinline__ uint32_t smem_u32(const void* p) {
    uint32_t a;
    asm("{ .reg .u64 t; cvta.to.shared.u64 t, %1; cvt.u32.u64 %0, t; }"
        : "=r"(a) : "l"(p));
    return a;
}
#define SW128(o) ((o) ^ (((o) >> 3) & 0x70))

__device__ __forceinline__ void cp16(uint32_t dst, const void* src) {
    asm volatile("cp.async.cg.shared.global [%0], [%1], 16;" :: "r"(dst), "l"(src));
}
__device__ __forceinline__ void cp16z(uint32_t dst, const void* src, bool v) {
    int sz = v ? 16 : 0;
    asm volatile("cp.async.cg.shared.global [%0], [%1], 16, %2;"
                 :: "r"(dst), "l"(src), "r"(sz));
}
#define CP_COMMIT() asm volatile("cp.async.commit_group;" ::: "memory")
#define CP_WAIT0()  asm volatile("cp.async.wait_group 0;" ::: "memory")
#define CP_WAIT1()  asm volatile("cp.async.wait_group 1;" ::: "memory")

__device__ __forceinline__ void ldm_x4(uint32_t (&r)[4], uint32_t addr) {
    asm volatile("ldmatrix.sync.aligned.m8n8.x4.shared.b16 {%0,%1,%2,%3}, [%4];"
                 : "=r"(r[0]), "=r"(r[1]), "=r"(r[2]), "=r"(r[3]) : "r"(addr));
}
__device__ __forceinline__ void mma16816(float* c, const uint32_t* a,
                                         uint32_t b0, uint32_t b1) {
    asm volatile(
        "mma.sync.aligned.m16n8k16.row.col.f32.bf16.bf16.f32 "
        "{%0,%1,%2,%3}, {%4,%5,%6,%7}, {%8,%9}, {%0,%1,%2,%3};"
        : "+f"(c[0]), "+f"(c[1]), "+f"(c[2]), "+f"(c[3])
        : "r"(a[0]), "r"(a[1]), "r"(a[2]), "r"(a[3]), "r"(b0), "r"(b1));
}

// ---------------- HMMA GEMM: C[M,N] = A[M,K] * B[N,K]^T, bf16 in, fp32 acc ---
// Tile 128x128, 8 warps (4m x 2n), K-chunk 64, 2-stage cp.async pipeline.
// MODE 0: bf16 store; 1: softplus(v+bias[n]) fp32; 2: x + gate*v fp32;
// MODE 3: x_proj split (dt bf16 padded / BC fp32)
template <int MODE>
__global__ void __launch_bounds__(256)
hgemm(const __nv_bfloat16* __restrict__ A, int lda,
      const __nv_bfloat16* __restrict__ Bw, int ldb,
      int N, int K,
      const float* __restrict__ bias,
      const float* __restrict__ xres,
      void* __restrict__ out0, int ldo) {
    extern __shared__ char smem[];
    const int tid = threadIdx.x;
    const int lane = tid & 31;
    const int wid = tid >> 5;
    const int wm = wid >> 1;        // 0..3
    const int wn = wid & 1;         // 0..1
    const int bm = blockIdx.y * 128;
    const int bn = blockIdx.x * 128;
    const uint32_t sbase = smem_u32(smem);
    constexpr int ABYTES = 128 * 128;
    constexpr int STAGE = 2 * ABYTES;

    auto load_chunk = [&](int c, int s) {
        uint32_t sa = sbase + s * STAGE;
        const char* gA = (const char*)A + (size_t)bm * lda * 2 + (size_t)c * 128;
        #pragma unroll
        for (int i = tid; i < 1024; i += 256) {
            int r = i >> 3, cb = (i & 7) << 4;
            cp16(sa + SW128(r * 128 + cb), gA + (size_t)r * lda * 2 + cb);
        }
        uint32_t sbb = sa + ABYTES;
        const char* gB = (const char*)Bw + (size_t)bn * ldb * 2 + (size_t)c * 128;
        #pragma unroll
        for (int i = tid; i < 1024; i += 256) {
            int r = i >> 3, cb = (i & 7) << 4;
            cp16z(sbb + SW128(r * 128 + cb), gB + (size_t)r * ldb * 2 + cb,
                  (bn + r) < N);
        }
    };

    float acc[2][8][4];
    #pragma unroll
    for (int i = 0; i < 2; i++)
        #pragma unroll
        for (int j = 0; j < 8; j++)
            #pragma unroll
            for (int v = 0; v < 4; v++) acc[i][j][v] = 0.f;

    const int nk = K >> 6;
    load_chunk(0, 0);
    CP_COMMIT();

    for (int c = 0; c < nk; c++) {
        int s = c & 1;
        if (c + 1 < nk) {
            load_chunk(c + 1, (c + 1) & 1);
            CP_COMMIT();
            CP_WAIT1();
        } else {
            CP_WAIT0();
        }
        __syncthreads();
        uint32_t sa = sbase + s * STAGE;
        uint32_t sbb = sa + ABYTES;
        const int rla = (lane & 15);
        const int cl16 = (lane >> 4) << 4;
        #pragma unroll
        for (int ks = 0; ks < 4; ks++) {
            uint32_t af[2][4], bf[4][4];
            int colb = ks * 32 + cl16;
            ldm_x4(af[0], sa + SW128((wm * 32 + rla) * 128 + colb));
            ldm_x4(af[1], sa + SW128((wm * 32 + 16 + rla) * 128 + colb));
            #pragma unroll
            for (int n2 = 0; n2 < 4; n2++)
                ldm_x4(bf[n2], sbb + SW128((wn * 64 + n2 * 16 + rla) * 128 + colb));
            #pragma unroll
            for (int mf = 0; mf < 2; mf++)
                #pragma unroll
                for (int n2 = 0; n2 < 4; n2++) {
                    mma16816(acc[mf][n2 * 2],     af[mf], bf[n2][0], bf[n2][2]);
                    mma16816(acc[mf][n2 * 2 + 1], af[mf], bf[n2][1], bf[n2][3]);
                }
        }
        __syncthreads();
    }

    // Epilogue
    const int g = lane >> 2, t = lane & 3;
    #pragma unroll
    for (int mf = 0; mf < 2; mf++) {
        #pragma unroll
        for (int nf = 0; nf < 8; nf++) {
            const float* cc = acc[mf][nf];
            int m0 = bm + wm * 32 + mf * 16 + g;
            int n0 = bn + wn * 64 + nf * 8 + t * 2;
            #pragma unroll
            for (int half = 0; half < 2; half++) {
                int m = m0 + half * 8;
                float v0 = cc[half * 2], v1 = cc[half * 2 + 1];
                if (MODE == 0) {
                    __nv_bfloat16* op = (__nv_bfloat16*)out0 + (size_t)m * ldo + n0;
                    *reinterpret_cast<__nv_bfloat162*>(op) =
                        __floats2bfloat162_rn(v0, v1);
                } else if (MODE == 1) {
                    float* op = (float*)out0 + (size_t)m * ldo + n0;
                    float a0 = v0 + bias[n0], a1 = v1 + bias[n0 + 1];
                    op[0] = (a0 > 20.f) ? a0 : log1pf(__expf(a0));
                    op[1] = (a1 > 20.f) ? a1 : log1pf(__expf(a1));
                } else if (MODE == 2) {
                    float* op = (float*)out0 + (size_t)m * ldo + n0;
                    const float* xr = xres + (size_t)m * ldo + n0;
                    const float* ga = g_ada + (m >> 11) * (3 * DD) + 2 * DD + n0;
                    op[0] = xr[0] + ga[0] * v0;
                    op[1] = xr[1] + ga[1] * v1;
                } else {  // MODE 3
                    #pragma unroll
                    for (int e = 0; e < 2; e++) {
                        int n = n0 + e;
                        float v = e ? v1 : v0;
                        if (n < 48) {
                            g_dt_bf[(size_t)m * 64 + n] = __float2bfloat16_rn(v);
                        } else if (n < 80) {
                            g_bc[(size_t)m * 32 + (n - 48)] = v;
                            if (n < 64)
                                g_dt_bf[(size_t)m * 64 + n] = __float2bfloat16_rn(0.f);
                        }
                    }
                }
            }
        }
    }
}

// ---------------- small kernels ----------------------------------------------
__global__ void cvt_bf16_kernel(const float* __restrict__ a,
                                __nv_bfloat16* __restrict__ o, int n) {
    int i = blockIdx.x * 256 + threadIdx.x;
    if (i < n) o[i] = __float2bfloat16_rn(a[i]);
}
__global__ void cvt_dtw_kernel(const float* __restrict__ w,
                               __nv_bfloat16* __restrict__ o) {
    int i = blockIdx.x * 256 + threadIdx.x;  // 1536*64
    if (i < DI * 64) {
        int r = i >> 6, c = i & 63;
        o[i] = __float2bfloat16_rn(c < DR ? w[r * DR + c] : 0.f);
    }
}

__global__ void ada_kernel(const float* __restrict__ c,
                           const float* __restrict__ ada_w,
                           const float* __restrict__ ada_b) {
    int warp = threadIdx.x >> 5, lane = threadIdx.x & 31;
    int j = blockIdx.x * 8 + warp;
    int b = blockIdx.y;
    const float* cr = c + b * (2 * DD);
    const float* wr = ada_w + (size_t)j * (2 * DD);
    float acc = 0.f;
    for (int k = lane; k < 2 * DD; k += 32) {
        float cv = cr[k];
        acc += (cv / (1.0f + __expf(-cv))) * wr[k];
    }
    #pragma unroll
    for (int o = 16; o; o >>= 1) acc += __shfl_down_sync(0xffffffffu, acc, o);
    if (lane == 0) g_ada[b * (3 * DD) + j] = acc + ada_b[j];
}

__global__ void ln_mod_kernel(const float* __restrict__ x,
                              const float* __restrict__ lnw,
                              const float* __restrict__ lnb) {
    int row = blockIdx.x;
    int b = row >> 11;
    const float* xr = x + (size_t)row * DD;
    int tid = threadIdx.x;
    float s = 0.f, s2 = 0.f;
    #pragma unroll
    for (int i = 0; i < 3; i++) {
        float v = xr[tid + i * 256];
        s += v; s2 += v * v;
    }
    #pragma unroll
    for (int o = 16; o; o >>= 1) {
        s  += __shfl_down_sync(0xffffffffu, s,  o);
        s2 += __shfl_down_sync(0xffffffffu, s2, o);
    }
    __shared__ float rs[8], rs2[8], smu, srstd;
    int warp = tid >> 5, lane = tid & 31;
    if (lane == 0) { rs[warp] = s; rs2[warp] = s2; }
    __syncthreads();
    if (tid == 0) {
        float S = 0.f, S2 = 0.f;
        #pragma unroll
        for (int w = 0; w < 8; w++) { S += rs[w]; S2 += rs2[w]; }
        float mu = S * (1.0f / DD);
        float var = S2 * (1.0f / DD) - mu * mu;
        smu = mu; srstd = rsqrtf(var + 1e-5f);
    }
    __syncthreads();
    float mu = smu, rstd = srstd;
    const float* adab = g_ada + b * (3 * DD);
    #pragma unroll
    for (int i = 0; i < 3; i++) {
        int j = tid + i * 256;
        float v = (xr[j] - mu) * rstd * lnw[j] + lnb[j];
        g_xm_bf[(size_t)row * DD + j] =
            __float2bfloat16_rn(v * (1.0f + adab[DD + j]) + adab[j]);
    }
}

// depthwise causal conv K=4 + silu; bf16 in (xi half of xz), fp32+bf16 u out
__global__ void conv_silu_kernel(const float* __restrict__ cw,
                                 const float* __restrict__ cb) {
    long long idx = (long long)blockIdx.x * 256 + threadIdx.x;  // over B*L*DI/2
    if (idx >= (long long)BB * LL * DI / 2) return;
    int d2 = (int)(idx % (DI / 2));
    long long bt = idx / (DI / 2);
    int t = (int)(bt % LL);
    int b = (int)(bt / LL);
    int d = d2 * 2;
    const __nv_bfloat162* base = reinterpret_cast<const __nv_bfloat162*>(
        g_xz_bf + ((size_t)b * LL) * (2 * DI) + d);
    const int rs = DI;
    float4 wa = *reinterpret_cast<const float4*>(cw + d * 4);
    float4 wb = *reinterpret_cast<const float4*>(cw + (d + 1) * 4);
    float a0 = cb[d], a1 = cb[d + 1];
    #pragma unroll
    for (int k = 0; k < 4; k++) {
        int tt = t - 3 + k;
        if (tt < 0) continue;
        float2 v = __bfloat1622float2(base[(size_t)tt * rs]);
        float w0 = (k == 0) ? wa.x : (k == 1) ? wa.y : (k == 2) ? wa.z : wa.w;
        float w1 = (k == 0) ? wb.x : (k == 1) ? wb.y : (k == 2) ? wb.z : wb.w;
        a0 += v.x * w0;
        a1 += v.y * w1;
    }
    float u0 = a0 / (1.0f + __expf(-a0));
    float u1 = a1 / (1.0f + __expf(-a1));
    size_t o = ((size_t)(b * LL + t)) * DI + d;
    *reinterpret_cast<float2*>(g_u + o) = make_float2(u0, u1);
    *reinterpret_cast<__nv_bfloat162*>(g_u_bf + o) = __floats2bfloat162_rn(u0, u1);
}

// ---------------- scan -------------------------------------------------------
__global__ void __launch_bounds__(128) scan_pass1(const float* __restrict__ A_log) {
    int d = blockIdx.x * 128 + threadIdx.x;
    int ch = blockIdx.y, b = blockIdx.z;
    float a[DS], h[DS];
    bool geo = true;
    #pragma unroll
    for (int s = 0; s < DS; s++) {
        a[s] = -__expf(A_log[(size_t)d * DS + s]);
        h[s] = 0.f;
    }
    #pragma unroll
    for (int s = 0; s < DS; s++) {
        float rr = a[s] / a[0];
        geo = geo && (fabsf(rr - (float)(s + 1)) < 1e-3f * (s + 1));
    }
    float S = 0.f;
    __shared__ float sB[8][DS];
    int t0 = ch * CLEN;
    for (int tt = 0; tt < CLEN; tt += 8) {
        __syncthreads();
        {
            int trow = threadIdx.x >> 4, s = threadIdx.x & 15;
            sB[trow][s] = g_bc[(size_t)(b * LL + t0 + tt + trow) * 32 + s];
        }
        __syncthreads();
        #pragma unroll
        for (int q = 0; q < 8; q++) {
            size_t off = (size_t)(b * LL + t0 + tt + q) * DI + d;
            float delta = g_delta[off];
            float du = delta * g_u[off];
            S += delta;
            if (geo) {
                float E = __expf(delta * a[0]);
                float dA = 1.f;
                #pragma unroll
                for (int s = 0; s < DS; s++) {
                    dA *= E;
                    h[s] = dA * h[s] + du * sB[q][s];
                }
            } else {
                #pragma unroll
                for (int s = 0; s < DS; s++) {
                    float dA = __expf(delta * a[s]);
                    h[s] = dA * h[s] + du * sB[q][s];
                }
            }
        }
    }
    size_t o = ((size_t)(b * DI + d) * NCH + ch) * DS;
    #pragma unroll
    for (int s = 0; s < DS; s++) {
        g_hend[o + s] = h[s];
        g_P[o + s] = __expf(a[s] * S);
    }
}

__global__ void scan_pass2() {
    int idx = blockIdx.x * 256 + threadIdx.x;
    if (idx >= BB * DI * DS) return;
    size_t base = (size_t)(idx >> 4) * (NCH * DS) + (idx & 15);
    float hi = 0.f;
    #pragma unroll
    for (int ch = 0; ch < NCH; ch++) {
        size_t o = base + (size_t)ch * DS;
        g_hinit[o] = hi;
        hi = g_P[o] * hi + g_hend[o];
    }
}

__global__ void __launch_bounds__(128) scan_pass3(const float* __restrict__ A_log,
                                                  const float* __restrict__ Dp) {
    int d = blockIdx.x * 128 + threadIdx.x;
    int ch = blockIdx.y, b = blockIdx.z;
    float a[DS], h[DS];
    bool geo = true;
    size_t hio = ((size_t)(b * DI + d) * NCH + ch) * DS;
    #pragma unroll
    for (int s = 0; s < DS; s++) {
        a[s] = -__expf(A_log[(size_t)d * DS + s]);
        h[s] = g_hinit[hio + s];
    }
    #pragma unroll
    for (int s = 0; s < DS; s++) {
        float rr = a[s] / a[0];
        geo = geo && (fabsf(rr - (float)(s + 1)) < 1e-3f * (s + 1));
    }
    float Dpd = Dp[d];
    __shared__ float sBC[8][32];
    int t0 = ch * CLEN;
    for (int tt = 0; tt < CLEN; tt += 8) {
        __syncthreads();
        #pragma unroll
        for (int r = 0; r < 2; r++) {
            int q = threadIdx.x + r * 128;
            int trow = q >> 5, cc = q & 31;
            sBC[trow][cc] = g_bc[(size_t)(b * LL + t0 + tt + trow) * 32 + cc];
        }
        __syncthreads();
        #pragma unroll
        for (int q = 0; q < 8; q++) {
            int t = t0 + tt + q;
            size_t off = (size_t)(b * LL + t) * DI + d;
            float delta = g_delta[off];
            float uv = g_u[off];
            float du = delta * uv;
            float y = 0.f;
            if (geo) {
                float E = __expf(delta * a[0]);
                float dA = 1.f;
                #pragma unroll
                for (int s = 0; s < DS; s++) {
                    dA *= E;
                    h[s] = dA * h[s] + du * sBC[q][s];
                    y += h[s] * sBC[q][DS + s];
                }
            } else {
                #pragma unroll
                for (int s = 0; s < DS; s++) {
                    float dA = __expf(delta * a[s]);
                    h[s] = dA * h[s] + du * sBC[q][s];
                    y += h[s] * sBC[q][DS + s];
                }
            }
            float z = __bfloat162float(g_xz_bf[(size_t)(b * LL + t) * (2 * DI) + DI + d]);
            float yv = y + uv * Dpd;
            g_y_bf[off] = __float2bfloat16_rn(yv * (z / (1.0f + __expf(-z))));
        }
    }
}

// ---------------- launch -----------------------------------------------------
extern "C" void kernel_launch(void* const* d_in, const int* in_sizes, int n_in,
                              void* d_out, int out_size) {
    const float* x         = (const float*)d_in[0];
    const float* c         = (const float*)d_in[1];
    const float* ln_w      = (const float*)d_in[2];
    const float* ln_b      = (const float*)d_in[3];
    const float* ada_w     = (const float*)d_in[4];
    const float* ada_b     = (const float*)d_in[5];
    const float* in_proj_w = (const float*)d_in[6];
    const float* conv_w    = (const float*)d_in[7];
    const float* conv_b    = (const float*)d_in[8];
    const float* x_proj_w  = (const float*)d_in[9];
    const float* dt_proj_w = (const float*)d_in[10];
    const float* dt_proj_b = (const float*)d_in[11];
    const float* A_log     = (const float*)d_in[12];
    const float* D_param   = (const float*)d_in[13];
    const float* out_proj_w= (const float*)d_in[14];
    float* out = (float*)d_out;

    __nv_bfloat16 *p_xm, *p_xz, *p_ubf, *p_dt, *p_dtw, *p_y, *p_w1, *p_w2, *p_xpw;
    float *p_delta;
    cudaGetSymbolAddress((void**)&p_xm,    g_xm_bf);
    cudaGetSymbolAddress((void**)&p_xz,    g_xz_bf);
    cudaGetSymbolAddress((void**)&p_ubf,   g_u_bf);
    cudaGetSymbolAddress((void**)&p_dt,    g_dt_bf);
    cudaGetSymbolAddress((void**)&p_dtw,   g_dtw);
    cudaGetSymbolAddress((void**)&p_y,     g_y_bf);
    cudaGetSymbolAddress((void**)&p_w1,    g_w1);
    cudaGetSymbolAddress((void**)&p_w2,    g_w2);
    cudaGetSymbolAddress((void**)&p_xpw,   g_xpw);
    cudaGetSymbolAddress((void**)&p_delta, g_delta);

    const int M = BB * LL;
    const int SMEM = 2 * 2 * 128 * 128;  // 65536
    cudaFuncSetAttribute(hgemm<0>, cudaFuncAttributeMaxDynamicSharedMemorySize, SMEM);
    cudaFuncSetAttribute(hgemm<1>, cudaFuncAttributeMaxDynamicSharedMemorySize, SMEM);
    cudaFuncSetAttribute(hgemm<2>, cudaFuncAttributeMaxDynamicSharedMemorySize, SMEM);
    cudaFuncSetAttribute(hgemm<3>, cudaFuncAttributeMaxDynamicSharedMemorySize, SMEM);

    // weight conversions
    cvt_bf16_kernel<<<(2 * DI * DD + 255) / 256, 256>>>(in_proj_w, p_w1, 2 * DI * DD);
    cvt_bf16_kernel<<<(DD * DI + 255) / 256, 256>>>(out_proj_w, p_w2, DD * DI);
    cvt_bf16_kernel<<<(80 * DI + 255) / 256, 256>>>(x_proj_w, p_xpw, 80 * DI);
    cvt_dtw_kernel<<<(DI * 64 + 255) / 256, 256>>>(dt_proj_w, p_dtw);

    ada_kernel<<<dim3(3 * DD / 8, BB), 256>>>(c, ada_w, ada_b);
    ln_mod_kernel<<<M, 256>>>(x, ln_w, ln_b);

    // xz = xm @ in_proj_w^T   (8192 x 3072 x 768)
    hgemm<0><<<dim3(3072 / 128, M / 128), 256, SMEM>>>(
        p_xm, DD, p_w1, DD, 3072, DD, nullptr, nullptr, p_xz, 3072);

    conv_silu_kernel<<<(BB * LL * DI / 2 + 255) / 256, 256>>>(conv_w, conv_b);

    // dbl = u @ x_proj_w^T    (8192 x 80 x 1536) -> dt_bf + bc
    hgemm<3><<<dim3(1, M / 128), 256, SMEM>>>(
        p_ubf, DI, p_xpw, DI, 80, DI, nullptr, nullptr, nullptr, 0);

    // delta = softplus(dt @ dt_proj_w^T + b)  (8192 x 1536 x 64pad)
    hgemm<1><<<dim3(DI / 128, M / 128), 256, SMEM>>>(
        p_dt, 64, p_dtw, 64, DI, 64, dt_proj_b, nullptr, p_delta, DI);

    scan_pass1<<<dim3(DI / 128, NCH, BB), 128>>>(A_log);
    scan_pass2<<<(BB * DI * DS + 255) / 256, 256>>>();
    scan_pass3<<<dim3(DI / 128, NCH, BB), 128>>>(A_log, D_param);

    // out = x + gate * (y @ out_proj_w^T)   (8192 x 768 x 1536)
    hgemm<2><<<dim3(DD / 128, M / 128), 256, SMEM>>>(
        p_y, DI, p_w2, DI, DD, DI, nullptr, x, out, DD);
}